// round 14
// baseline (speedup 1.0000x reference)
#include <cuda_runtime.h>

#define BB 128
#define LL 128
#define TNN 32
#define ST 512
#define SW 16
#define K2T 256
#define K2W 8

typedef unsigned long long ull;

// inter-kernel scratch (device globals: allowed; no allocation)
__device__ float g_mark[BB * 129 * 68];
__device__ int   g_rnz[BB * 129];

// ---------- packed f32x2 helpers ----------
__device__ __forceinline__ ull pack2(float x, float y) {
    ull r; asm("mov.b64 %0, {%1,%2};" : "=l"(r) : "f"(x), "f"(y)); return r;
}
__device__ __forceinline__ void unpack2(ull v, float& x, float& y) {
    asm("mov.b64 {%0,%1}, %2;" : "=f"(x), "=f"(y) : "l"(v));
}
__device__ __forceinline__ void fma2(ull& d, ull a, ull b) {
    asm("fma.rn.f32x2 %0, %1, %2, %0;" : "+l"(d) : "l"(a), "l"(b));
}
__device__ __forceinline__ float pairsum(ull v) {
    float x, y; unpack2(v, x, y); return x + y;
}
__device__ __forceinline__ float leaky(float v) { return v > 0.f ? v : 0.01f * v; }

// Conflict-free k-pair packed index for a [K x 128] weight (scan GEMM1 path):
__device__ __forceinline__ int pack_idx_128(int k, int h) {
    return ((k >> 1) << 8) + (((h >> 1) & 1) << 7) + (h & ~3) + ((h & 1) << 1) + (k & 1);
}
// Half-split k-pair pack for 8row x 64col tasks (score kernel):
// dest = kp*256 + (h>=64)*128 + (h%64)*2 + (k&1); lane l reads 16B at +l*16.
__device__ __forceinline__ int pack_idx_h64(int k, int h) {
    return ((k >> 1) << 8) + ((h >> 6) << 7) + ((h & 63) << 1) + (k & 1);
}

// 4-row K=68 microkernel with x staging (scan; round-6 proven config).
__device__ __forceinline__ void gemm4_k68p(const float* __restrict__ smk,
                                           const int* roff,
                                           const float* __restrict__ wp,
                                           int h0, ull acc[4][4]) {
#pragma unroll 1
    for (int k4 = 0; k4 < 17; k4++) {
        ulonglong2 x[4];
#pragma unroll
        for (int q = 0; q < 4; q++)
            x[q] = *(const ulonglong2*)(smk + roff[q] + 4 * k4);
#pragma unroll
        for (int half = 0; half < 2; half++) {
            const int kp = 2 * k4 + half;
            ulonglong2 wa = *(const ulonglong2*)(wp + kp * 256 + h0);
            ulonglong2 wb = *(const ulonglong2*)(wp + kp * 256 + 128 + h0);
#pragma unroll
            for (int q = 0; q < 4; q++) {
                ull xp = half ? x[q].y : x[q].x;
                fma2(acc[q][0], xp, wa.x);
                fma2(acc[q][1], xp, wa.y);
                fma2(acc[q][2], xp, wb.x);
                fma2(acc[q][3], xp, wb.y);
            }
        }
    }
}

// 8-row x 64-col K=68 microkernel (score): weights amortized over 8 rows.
// Lane l owns cols half*64 + 2l, +1. acc[q][0/1] = k-even/odd partial pairs.
__device__ __forceinline__ void gemm8_h64(const float* __restrict__ smk,
                                          const int* roff,
                                          const float* __restrict__ wbase,
                                          ull acc[8][2]) {
#pragma unroll 1
    for (int k4 = 0; k4 < 17; k4++) {
        ulonglong2 x[8];
#pragma unroll
        for (int q = 0; q < 8; q++)
            x[q] = *(const ulonglong2*)(smk + roff[q] + 4 * k4);
#pragma unroll
        for (int hf = 0; hf < 2; hf++) {
            const int kp = 2 * k4 + hf;
            ulonglong2 wv = *(const ulonglong2*)(wbase + (kp << 8));
#pragma unroll
            for (int q = 0; q < 8; q++) {
                ull xp = hf ? x[q].y : x[q].x;
                fma2(acc[q][0], xp, wv.x);
                fma2(acc[q][1], xp, wv.y);
            }
        }
    }
}

// ---------- scan kernel shared memory layout (floats; round-13 verbatim) ----------
#define OFF_W1P  0
#define OFF_W1C  8704
#define OFF_W2P  17408
#define OFF_MARK 25600
#define OFF_WB   34372
#define OFF_LH   42628
#define OFF_PMAX 51076
#define OFF_PSUM 51588
#define OFF_PCB1 52164
#define OFF_PCB2 52292
#define OFF_BD   52356
#define OFF_G    52996
#define OFF_C    55108
#define OFF_TE   57156
#define OFF_RNZ  57284
#define OFF_TLZ  57413
#define OFF_GNZ  57542
#define OFF_RLIST 57576
#define OFF_NNZ  57704
#define SMEM_FLOATS 57708
#define SMEM_BYTES (SMEM_FLOATS * 4)

__global__ __launch_bounds__(ST, 1)
void petri_scan(const float* __restrict__ bd,   const float* __restrict__ G,
                const float* __restrict__ C,    const float* __restrict__ Temb,
                const float* __restrict__ pcW1, const float* __restrict__ pcb1,
                const float* __restrict__ pcW2, const float* __restrict__ pcb2)
{
    extern __shared__ float sm[];
    const int tid  = threadIdx.x;
    const int lane = tid & 31;
    const int w    = tid >> 5;
    const int b    = blockIdx.x;
    const int h0   = lane * 4;
    const int n2   = lane * 2;

    float* sW1p  = sm + OFF_W1P;
    float* sW1c  = sm + OFF_W1C;
    float* sW2p  = sm + OFF_W2P;
    float* sMark = sm + OFF_MARK;
    float* sWB   = sm + OFF_WB;
    float* sLH   = sm + OFF_LH;
    float* sPMAX = sm + OFF_PMAX;
    float* sPSUM = sm + OFF_PSUM;
    float* sPcb1 = sm + OFF_PCB1;
    float* sPcb2 = sm + OFF_PCB2;
    float* sBD   = sm + OFF_BD;
    float* sG    = sm + OFF_G;
    float* sC    = sm + OFF_C;
    float* sTe   = sm + OFF_TE;
    int*   rownz = (int*)(sm + OFF_RNZ);
    int*   tailz = (int*)(sm + OFF_TLZ);
    int*   gnzf  = (int*)(sm + OFF_GNZ);
    int*   rlist = (int*)(sm + OFF_RLIST);
    int*   snnz  = (int*)(sm + OFF_NNZ);

    for (int idx = tid; idx < 68 * 128; idx += ST) {
        int k = idx >> 7, h = idx & 127;
        sW1p[pack_idx_128(k, h)] = pcW1[idx];
        sW1c[idx] = pcW1[68 * 128 + idx];
    }
    for (int idx = tid; idx < 128 * 64; idx += ST) {
        int k = idx >> 6, n = idx & 63;
        sW2p[((k >> 1) << 7) + (n << 1) + (k & 1)] = pcW2[idx];
    }
    if (tid < 128) sPcb1[tid] = pcb1[tid];
    else if (tid < 192) sPcb2[tid - 128] = pcb2[tid - 128];
    for (int i = tid; i < 640; i += ST) sBD[i] = bd[b * 640 + i];
    for (int i = tid; i < 33 * 64; i += ST) sG[i] = fmaxf(G[i], 0.f);
    for (int i = tid; i < 32 * 64; i += ST) sC[i] = fmaxf(C[i], 0.f);
    if (tid < 128) sTe[tid] = Temb[tid];
    for (int i = tid; i < 129 * 68; i += ST) sMark[i] = 0.f;
    if (tid < 129) { rownz[tid] = 0; tailz[tid] = 1; }
    if (tid == 200) *snnz = 0;
    __syncthreads();
    if (tid < 33) {
        int nz = 0;
        for (int c = 0; c < 64; c++) nz |= (sG[tid * 64 + c] != 0.f);
        gnzf[tid] = nz;
    } else if (tid >= 64 && tid < 128) {
        sMark[tid - 64] = sG[tid - 64];
    }
    __syncthreads();
    if (tid == 0) rownz[0] = gnzf[0];

    // precompute 32 base vectors (pcb1 folded in)
    for (int idx = tid; idx < 32 * 128; idx += ST) {
        const int aa = idx >> 7, h = idx & 127;
        const float* cv = sC + aa * 64;
        const float* wc = sW1c + h;
        float s = sPcb1[h];
#pragma unroll 4
        for (int j = 0; j < 64; j++)
            s = fmaf(cv[j], wc[j << 7], s);
        const float* tv = sTe + aa * 4;
#pragma unroll
        for (int j = 0; j < 4; j++)
            s = fmaf(tv[j], wc[(64 + j) << 7], s);
        sWB[idx] = s;
    }
    __syncthreads();
    for (int idx = tid; idx < 32 * 128; idx += ST) sW1c[idx] = sWB[idx];
    __syncthreads();
    const float* sBaseAll = sW1c;

    float* lhw = sLH + w * 528;

    for (int i = 0; i < LL; i++) {
        const int a = (int)sBD[i];
        if (a <= 0 || a == TNN + 1) continue;
        const int ai = a - 1, gi = a;
        const int nrows = i + 1;

        if (tid < 64)       sMark[nrows * 68 + tid] = sG[gi * 64 + tid];
        else if (tid < 68)  sMark[nrows * 68 + tid] = sBD[(tid - 63) * 128 + i];
        else if (tid == 68) {
            float t0 = sBD[128 + i], t1 = sBD[256 + i],
                  t2 = sBD[384 + i], t3 = sBD[512 + i];
            int tz = (t0 == 0.f) && (t1 == 0.f) && (t2 == 0.f) && (t3 == 0.f);
            tailz[nrows] = tz;
            rownz[nrows] = (gnzf[gi] != 0) || !tz;
        } else if (tid >= 128 && tid < 256) {
            const int r = tid - 128;
            if (r < nrows && rownz[r]) {
                int p = atomicAdd(snnz, 1);
                rlist[p] = r;
            }
        }
        __syncthreads();

        const int nn = *snnz;
        const int ntiles = (nn + 3) >> 2;

        for (int tile = w; tile < ntiles; tile += SW) {
            const int r0 = tile * 4;
            int rows[4], roff[4];
#pragma unroll
            for (int q = 0; q < 4; q++) {
                rows[q] = rlist[min(r0 + q, nn - 1)];
                roff[q] = rows[q] * 68;
            }

            ull acc[4][4];
            {
                float4 bb = *(const float4*)(sBaseAll + ai * 128 + h0);
                ull i0 = pack2(bb.x, 0.f), i1 = pack2(bb.y, 0.f),
                    i2 = pack2(bb.z, 0.f), i3 = pack2(bb.w, 0.f);
#pragma unroll
                for (int q = 0; q < 4; q++) {
                    acc[q][0] = i0; acc[q][1] = i1; acc[q][2] = i2; acc[q][3] = i3;
                }
            }
            gemm4_k68p(sMark, roff, sW1p, h0, acc);
#pragma unroll
            for (int q = 0; q < 4; q++)
                *(float4*)(lhw + q * 132 + h0) =
                    make_float4(leaky(pairsum(acc[q][0])), leaky(pairsum(acc[q][1])),
                                leaky(pairsum(acc[q][2])), leaky(pairsum(acc[q][3])));
            __syncwarp();

            ull acc2[4][2];
            {
                float2 pb = *(const float2*)(sPcb2 + n2);
                ull b0 = pack2(pb.x, 0.f), b1 = pack2(pb.y, 0.f);
#pragma unroll
                for (int q = 0; q < 4; q++) { acc2[q][0] = b0; acc2[q][1] = b1; }
            }
#pragma unroll 1
            for (int k4 = 0; k4 < 32; k4++) {
                ulonglong2 x[4];
#pragma unroll
                for (int q = 0; q < 4; q++)
                    x[q] = *(const ulonglong2*)(lhw + q * 132 + 4 * k4);
#pragma unroll
                for (int half = 0; half < 2; half++) {
                    const int kp = 2 * k4 + half;
                    ulonglong2 w2 = *(const ulonglong2*)(sW2p + kp * 128 + n2 * 2);
#pragma unroll
                    for (int q = 0; q < 4; q++) {
                        ull xp = half ? x[q].y : x[q].x;
                        fma2(acc2[q][0], xp, w2.x);
                        fma2(acc2[q][1], xp, w2.y);
                    }
                }
            }
#pragma unroll
            for (int q = 0; q < 4; q++) {
                if (r0 + q < nn)
                    *(float2*)(sWB + rows[q] * 64 + n2) =
                        make_float2(pairsum(acc2[q][0]), pairsum(acc2[q][1]));
            }
            __syncwarp();
        }
        __syncthreads();

        {
            const int n = tid & 63, c = tid >> 6;
            float m = -1e30f;
            for (int j = c; j < nn; j += 8)
                m = fmaxf(m, sWB[rlist[j] * 64 + n]);
            sPMAX[c * 64 + n] = m;
        }
        __syncthreads();
        {
            const int n = tid & 63, c = tid >> 6;
            float mm = sPMAX[n];
#pragma unroll
            for (int c2 = 1; c2 < 8; c2++) mm = fmaxf(mm, sPMAX[c2 * 64 + n]);
            float s = 0.f;
            for (int j = c; j < nn; j += 8) {
                float e = __expf(sWB[rlist[j] * 64 + n] - mm);
                sWB[rlist[j] * 64 + n] = e;
                s += e;
            }
            sPSUM[c * 64 + n] = s;
        }
        __syncthreads();

        if (nn > 0) {
            float s0 = 0.f, s1 = 0.f;
#pragma unroll
            for (int c = 0; c < 8; c++) { s0 += sPSUM[c * 64 + lane]; s1 += sPSUM[c * 64 + lane + 32]; }
            const float sc0 = sC[ai * 64 + lane] / s0;
            const float sc1 = sC[ai * 64 + lane + 32] / s1;
            for (int j = w; j < nn; j += SW) {
                const int r = rlist[j];
                float v0 = fmaxf(sMark[r * 68 + lane]      - sWB[r * 64 + lane]      * sc0, 0.f);
                float v1 = fmaxf(sMark[r * 68 + lane + 32] - sWB[r * 64 + lane + 32] * sc1, 0.f);
                sMark[r * 68 + lane]      = v0;
                sMark[r * 68 + lane + 32] = v1;
                unsigned nzb = __ballot_sync(0xffffffffu, (v0 != 0.f) || (v1 != 0.f));
                if (lane == 0) rownz[r] = (nzb != 0) || (tailz[r] == 0);
            }
        }
        if (tid == 0) *snnz = 0;
        __syncthreads();
    }

    for (int i = tid; i < 129 * 68; i += ST) g_mark[b * 8772 + i] = sMark[i];
    for (int i = tid; i < 129; i += ST)      g_rnz[b * 129 + i]  = rownz[i];
}

// ---------- scoring kernel: 8-row x 64-col tasks (crossbar cut) ----------
#define O2_JC   0        /* 8704 */
#define O2_JT   8704     /* 8704 */
#define O2_MK   17408    /* 8772 */
#define O2_JCB  26180    /* 128 */
#define O2_JTB  26308    /* 128 */
#define O2_JW2  26436    /* 128 */
#define O2_JF   26564    /* 128 */
#define O2_POOL 26692    /* 128 */
#define O2_JTP  26820    /* 264 : per-(rowpos,half) jt partial dots */
#define O2_RL   27084    /* 132 ints */
#define O2_NNZ  27216    /* 1 int */
#define SMEM2_FLOATS 27220
#define SMEM2_BYTES (SMEM2_FLOATS * 4)

__global__ __launch_bounds__(K2T, 2)
void score_kernel(const float* __restrict__ jcW1, const float* __restrict__ jcb1,
                  const float* __restrict__ jfW,  const float* __restrict__ jfb,
                  const float* __restrict__ jtW1, const float* __restrict__ jtb1,
                  const float* __restrict__ jtW2, const float* __restrict__ jtb2,
                  float* __restrict__ out)
{
    extern __shared__ float sm[];
    const int tid  = threadIdx.x;
    const int lane = tid & 31;
    const int w    = tid >> 5;
    const int t    = blockIdx.x;
    const int b    = blockIdx.y;

    float* sJc   = sm + O2_JC;
    float* sJt   = sm + O2_JT;
    float* sMk   = sm + O2_MK;
    float* sjcb  = sm + O2_JCB;
    float* sjtb  = sm + O2_JTB;
    float* sjw2  = sm + O2_JW2;
    float* sjf   = sm + O2_JF;
    float* spool = sm + O2_POOL;
    float* sjtp  = sm + O2_JTP;
    int*   rlist = (int*)(sm + O2_RL);
    int*   snnz  = (int*)(sm + O2_NNZ);

    for (int idx = tid; idx < 68 * 128; idx += K2T) {
        int k = idx >> 7, h = idx & 127;
        int d = pack_idx_h64(k, h);
        sJc[d] = jcW1[t * 8704 + idx];
        sJt[d] = jtW1[t * 8704 + idx];
    }
    for (int idx = tid; idx < 2193; idx += K2T)
        ((float4*)sMk)[idx] = ((const float4*)(g_mark + b * 8772))[idx];
    if (tid < 128) {
        sjcb[tid]  = jcb1[t * 128 + tid];
        sjtb[tid]  = jtb1[t * 128 + tid];
        sjw2[tid]  = jtW2[t * 128 + tid];
        sjf[tid]   = jfW[tid];
        spool[tid] = 0.f;
    }
    if (tid == 192) *snnz = 0;
    __syncthreads();

    if (tid < 129) {
        if (g_rnz[b * 129 + tid]) {
            int p = atomicAdd(snnz, 1);
            rlist[p] = tid;
        }
    }
    __syncthreads();
    const int nn = *snnz;
    const int zr = (nn < 129);
    const int noct   = (nn + 7) >> 3;
    const int ntasks = noct * 2;
    const float jtb2v = jtb2[t];

    // ---- jc path: tasks = (row-octet, h-half); lane owns 2 cols of its half ----
    for (int tau = w; tau < ntasks; tau += K2W) {
        const int oct  = tau >> 1;
        const int half = tau & 1;
        const int r0   = oct * 8;
        const int hh   = half * 64 + 2 * lane;
        int roff[8];
#pragma unroll
        for (int q = 0; q < 8; q++) roff[q] = rlist[min(r0 + q, nn - 1)] * 68;
        ull acc[8][2];
        {
            ull b0 = pack2(sjcb[hh], 0.f), b1 = pack2(sjcb[hh + 1], 0.f);
#pragma unroll
            for (int q = 0; q < 8; q++) { acc[q][0] = b0; acc[q][1] = b1; }
        }
        gemm8_h64(sMk, roff, sJc + (half << 7) + (lane << 2), acc);
        float pp0 = 0.f, pp1 = 0.f;
#pragma unroll
        for (int q = 0; q < 8; q++) {
            if (r0 + q < nn) {
                pp0 += leaky(pairsum(acc[q][0]));
                pp1 += leaky(pairsum(acc[q][1]));
            }
        }
        atomicAdd(&spool[hh],     pp0);
        atomicAdd(&spool[hh + 1], pp1);
    }

    // ---- jt path: per-(rowpos, half) partial dot into sjtp ----
    for (int tau = w; tau < ntasks; tau += K2W) {
        const int oct  = tau >> 1;
        const int half = tau & 1;
        const int r0   = oct * 8;
        const int hh   = half * 64 + 2 * lane;
        int roff[8];
#pragma unroll
        for (int q = 0; q < 8; q++) roff[q] = rlist[min(r0 + q, nn - 1)] * 68;
        ull acc[8][2];
        {
            ull b0 = pack2(sjtb[hh], 0.f), b1 = pack2(sjtb[hh + 1], 0.f);
#pragma unroll
            for (int q = 0; q < 8; q++) { acc[q][0] = b0; acc[q][1] = b1; }
        }
        gemm8_h64(sMk, roff, sJt + (half << 7) + (lane << 2), acc);
        const float w2a = sjw2[hh], w2b = sjw2[hh + 1];
#pragma unroll
        for (int q = 0; q < 8; q++) {
            float d = leaky(pairsum(acc[q][0])) * w2a + leaky(pairsum(acc[q][1])) * w2b;
            d += __shfl_xor_sync(0xffffffffu, d, 16);
            d += __shfl_xor_sync(0xffffffffu, d, 8);
            d += __shfl_xor_sync(0xffffffffu, d, 4);
            d += __shfl_xor_sync(0xffffffffu, d, 2);
            d += __shfl_xor_sync(0xffffffffu, d, 1);
            if (lane == 0 && r0 + q < nn) sjtp[(r0 + q) * 2 + half] = d;
        }
    }
    __syncthreads();

    // ---- combine (warp 0) ----
    if (w == 0) {
        const int h0 = lane * 4;
        const float w2a = sjw2[h0], w2b = sjw2[h0 + 1],
                    w2c = sjw2[h0 + 2], w2d = sjw2[h0 + 3];
        // zero-row jt score
        float zs = leaky(sjtb[h0])     * w2a + leaky(sjtb[h0 + 1]) * w2b
                 + leaky(sjtb[h0 + 2]) * w2c + leaky(sjtb[h0 + 3]) * w2d;
        zs += __shfl_xor_sync(0xffffffffu, zs, 16);
        zs += __shfl_xor_sync(0xffffffffu, zs, 8);
        zs += __shfl_xor_sync(0xffffffffu, zs, 4);
        zs += __shfl_xor_sync(0xffffffffu, zs, 2);
        zs += __shfl_xor_sync(0xffffffffu, zs, 1);

        // jt max over nonzero rows
        float tmax = zr ? (zs + jtb2v) : -1e30f;
        for (int j = lane; j < nn; j += 32)
            tmax = fmaxf(tmax, sjtp[2 * j] + sjtp[2 * j + 1] + jtb2v);
        tmax = fmaxf(tmax, __shfl_xor_sync(0xffffffffu, tmax, 16));
        tmax = fmaxf(tmax, __shfl_xor_sync(0xffffffffu, tmax, 8));
        tmax = fmaxf(tmax, __shfl_xor_sync(0xffffffffu, tmax, 4));
        tmax = fmaxf(tmax, __shfl_xor_sync(0xffffffffu, tmax, 2));
        tmax = fmaxf(tmax, __shfl_xor_sync(0xffffffffu, tmax, 1));

        float pr = spool[lane]      * sjf[lane]
                 + spool[lane + 32] * sjf[lane + 32]
                 + spool[lane + 64] * sjf[lane + 64]
                 + spool[lane + 96] * sjf[lane + 96];
        pr += __shfl_xor_sync(0xffffffffu, pr, 16);
        pr += __shfl_xor_sync(0xffffffffu, pr, 8);
        pr += __shfl_xor_sync(0xffffffffu, pr, 4);
        pr += __shfl_xor_sync(0xffffffffu, pr, 2);
        pr += __shfl_xor_sync(0xffffffffu, pr, 1);
        if (lane == 0) {
            float res = 1.f / (1.f + expf(-(pr + jfb[0])));
            res = fmaxf(res, 1e-5f);
            out[b * TNN + t] = res * tmax - 0.01f * expf(res);
        }
    }
}

// no-op kernel: shifts ncu's launch counter so -s 5 -c 1 captures petri_scan
__global__ void dummy_k() {}

extern "C" void kernel_launch(void* const* d_in, const int* in_sizes, int n_in,
                              void* d_out, int out_size) {
    (void)in_sizes; (void)n_in; (void)out_size;
    cudaFuncSetAttribute(petri_scan,
                         cudaFuncAttributeMaxDynamicSharedMemorySize, SMEM_BYTES);
    cudaFuncSetAttribute(score_kernel,
                         cudaFuncAttributeMaxDynamicSharedMemorySize, SMEM2_BYTES);
    petri_scan<<<BB, ST, SMEM_BYTES>>>(
        (const float*)d_in[0], (const float*)d_in[1], (const float*)d_in[2],
        (const float*)d_in[3], (const float*)d_in[4], (const float*)d_in[5],
        (const float*)d_in[6], (const float*)d_in[7]);
    score_kernel<<<dim3(TNN, BB), K2T, SMEM2_BYTES>>>(
        (const float*)d_in[8],  (const float*)d_in[9],  (const float*)d_in[10],
        (const float*)d_in[11], (const float*)d_in[12], (const float*)d_in[13],
        (const float*)d_in[14], (const float*)d_in[15], (float*)d_out);
    // 5 launches/call => ncu (-s 5 -c 1) captures launch #6 = call 2's petri_scan
    dummy_k<<<1, 1>>>();
    dummy_k<<<1, 1>>>();
    dummy_k<<<1, 1>>>();
}

// round 15
// speedup vs baseline: 1.0639x; 1.0639x over previous
#include <cuda_runtime.h>

#define BB 128
#define LL 128
#define TNN 32
#define ST 512
#define SW 16
#define K2T 256
#define K2W 8

typedef unsigned long long ull;

// inter-kernel scratch (device globals: allowed; no allocation)
__device__ float g_mark[BB * 129 * 68];
__device__ int   g_rnz[BB * 129];

// ---------- packed f32x2 helpers ----------
__device__ __forceinline__ ull pack2(float x, float y) {
    ull r; asm("mov.b64 %0, {%1,%2};" : "=l"(r) : "f"(x), "f"(y)); return r;
}
__device__ __forceinline__ void unpack2(ull v, float& x, float& y) {
    asm("mov.b64 {%0,%1}, %2;" : "=f"(x), "=f"(y) : "l"(v));
}
__device__ __forceinline__ void fma2(ull& d, ull a, ull b) {
    asm("fma.rn.f32x2 %0, %1, %2, %0;" : "+l"(d) : "l"(a), "l"(b));
}
__device__ __forceinline__ float pairsum(ull v) {
    float x, y; unpack2(v, x, y); return x + y;
}
__device__ __forceinline__ float leaky(float v) { return v > 0.f ? v : 0.01f * v; }

// Conflict-free k-pair packed index for a [K x 128] weight:
__device__ __forceinline__ int pack_idx_128(int k, int h) {
    return ((k >> 1) << 8) + (((h >> 1) & 1) << 7) + (h & ~3) + ((h & 1) << 1) + (k & 1);
}

// 4-row K=68 microkernel with x staging (proven optimum for this shape).
__device__ __forceinline__ void gemm4_k68p(const float* __restrict__ smk,
                                           const int* roff,
                                           const float* __restrict__ wp,
                                           int h0, ull acc[4][4]) {
#pragma unroll 1
    for (int k4 = 0; k4 < 17; k4++) {
        ulonglong2 x[4];
#pragma unroll
        for (int q = 0; q < 4; q++)
            x[q] = *(const ulonglong2*)(smk + roff[q] + 4 * k4);
#pragma unroll
        for (int half = 0; half < 2; half++) {
            const int kp = 2 * k4 + half;
            ulonglong2 wa = *(const ulonglong2*)(wp + kp * 256 + h0);
            ulonglong2 wb = *(const ulonglong2*)(wp + kp * 256 + 128 + h0);
#pragma unroll
            for (int q = 0; q < 4; q++) {
                ull xp = half ? x[q].y : x[q].x;
                fma2(acc[q][0], xp, wa.x);
                fma2(acc[q][1], xp, wa.y);
                fma2(acc[q][2], xp, wb.x);
                fma2(acc[q][3], xp, wb.y);
            }
        }
    }
}

// ---------- scan kernel shared memory layout (floats; round-13 verbatim) ----------
#define OFF_W1P  0
#define OFF_W1C  8704
#define OFF_W2P  17408
#define OFF_MARK 25600
#define OFF_WB   34372
#define OFF_LH   42628
#define OFF_PMAX 51076
#define OFF_PSUM 51588
#define OFF_PCB1 52164
#define OFF_PCB2 52292
#define OFF_BD   52356
#define OFF_G    52996
#define OFF_C    55108
#define OFF_TE   57156
#define OFF_RNZ  57284
#define OFF_TLZ  57413
#define OFF_GNZ  57542
#define OFF_RLIST 57576
#define OFF_NNZ  57704
#define SMEM_FLOATS 57708
#define SMEM_BYTES (SMEM_FLOATS * 4)

__global__ __launch_bounds__(ST, 1)
void petri_scan(const float* __restrict__ bd,   const float* __restrict__ G,
                const float* __restrict__ C,    const float* __restrict__ Temb,
                const float* __restrict__ pcW1, const float* __restrict__ pcb1,
                const float* __restrict__ pcW2, const float* __restrict__ pcb2)
{
    extern __shared__ float sm[];
    const int tid  = threadIdx.x;
    const int lane = tid & 31;
    const int w    = tid >> 5;
    const int b    = blockIdx.x;
    const int h0   = lane * 4;
    const int n2   = lane * 2;

    float* sW1p  = sm + OFF_W1P;
    float* sW1c  = sm + OFF_W1C;
    float* sW2p  = sm + OFF_W2P;
    float* sMark = sm + OFF_MARK;
    float* sWB   = sm + OFF_WB;
    float* sLH   = sm + OFF_LH;
    float* sPMAX = sm + OFF_PMAX;
    float* sPSUM = sm + OFF_PSUM;
    float* sPcb1 = sm + OFF_PCB1;
    float* sPcb2 = sm + OFF_PCB2;
    float* sBD   = sm + OFF_BD;
    float* sG    = sm + OFF_G;
    float* sC    = sm + OFF_C;
    float* sTe   = sm + OFF_TE;
    int*   rownz = (int*)(sm + OFF_RNZ);
    int*   tailz = (int*)(sm + OFF_TLZ);
    int*   gnzf  = (int*)(sm + OFF_GNZ);
    int*   rlist = (int*)(sm + OFF_RLIST);
    int*   snnz  = (int*)(sm + OFF_NNZ);

    for (int idx = tid; idx < 68 * 128; idx += ST) {
        int k = idx >> 7, h = idx & 127;
        sW1p[pack_idx_128(k, h)] = pcW1[idx];
        sW1c[idx] = pcW1[68 * 128 + idx];
    }
    for (int idx = tid; idx < 128 * 64; idx += ST) {
        int k = idx >> 6, n = idx & 63;
        sW2p[((k >> 1) << 7) + (n << 1) + (k & 1)] = pcW2[idx];
    }
    if (tid < 128) sPcb1[tid] = pcb1[tid];
    else if (tid < 192) sPcb2[tid - 128] = pcb2[tid - 128];
    for (int i = tid; i < 640; i += ST) sBD[i] = bd[b * 640 + i];
    for (int i = tid; i < 33 * 64; i += ST) sG[i] = fmaxf(G[i], 0.f);
    for (int i = tid; i < 32 * 64; i += ST) sC[i] = fmaxf(C[i], 0.f);
    if (tid < 128) sTe[tid] = Temb[tid];
    for (int i = tid; i < 129 * 68; i += ST) sMark[i] = 0.f;
    if (tid < 129) { rownz[tid] = 0; tailz[tid] = 1; }
    if (tid == 200) *snnz = 0;
    __syncthreads();
    if (tid < 33) {
        int nz = 0;
        for (int c = 0; c < 64; c++) nz |= (sG[tid * 64 + c] != 0.f);
        gnzf[tid] = nz;
    } else if (tid >= 64 && tid < 128) {
        sMark[tid - 64] = sG[tid - 64];
    }
    __syncthreads();
    if (tid == 0) rownz[0] = gnzf[0];

    // precompute 32 base vectors (pcb1 folded in)
    for (int idx = tid; idx < 32 * 128; idx += ST) {
        const int aa = idx >> 7, h = idx & 127;
        const float* cv = sC + aa * 64;
        const float* wc = sW1c + h;
        float s = sPcb1[h];
#pragma unroll 4
        for (int j = 0; j < 64; j++)
            s = fmaf(cv[j], wc[j << 7], s);
        const float* tv = sTe + aa * 4;
#pragma unroll
        for (int j = 0; j < 4; j++)
            s = fmaf(tv[j], wc[(64 + j) << 7], s);
        sWB[idx] = s;
    }
    __syncthreads();
    for (int idx = tid; idx < 32 * 128; idx += ST) sW1c[idx] = sWB[idx];
    __syncthreads();
    const float* sBaseAll = sW1c;

    float* lhw = sLH + w * 528;

    for (int i = 0; i < LL; i++) {
        const int a = (int)sBD[i];
        if (a <= 0 || a == TNN + 1) continue;
        const int ai = a - 1, gi = a;
        const int nrows = i + 1;

        if (tid < 64)       sMark[nrows * 68 + tid] = sG[gi * 64 + tid];
        else if (tid < 68)  sMark[nrows * 68 + tid] = sBD[(tid - 63) * 128 + i];
        else if (tid == 68) {
            float t0 = sBD[128 + i], t1 = sBD[256 + i],
                  t2 = sBD[384 + i], t3 = sBD[512 + i];
            int tz = (t0 == 0.f) && (t1 == 0.f) && (t2 == 0.f) && (t3 == 0.f);
            tailz[nrows] = tz;
            rownz[nrows] = (gnzf[gi] != 0) || !tz;
        } else if (tid >= 128 && tid < 256) {
            const int r = tid - 128;
            if (r < nrows && rownz[r]) {
                int p = atomicAdd(snnz, 1);
                rlist[p] = r;
            }
        }
        __syncthreads();

        const int nn = *snnz;
        const int ntiles = (nn + 3) >> 2;

        for (int tile = w; tile < ntiles; tile += SW) {
            const int r0 = tile * 4;
            int rows[4], roff[4];
#pragma unroll
            for (int q = 0; q < 4; q++) {
                rows[q] = rlist[min(r0 + q, nn - 1)];
                roff[q] = rows[q] * 68;
            }

            ull acc[4][4];
            {
                float4 bb = *(const float4*)(sBaseAll + ai * 128 + h0);
                ull i0 = pack2(bb.x, 0.f), i1 = pack2(bb.y, 0.f),
                    i2 = pack2(bb.z, 0.f), i3 = pack2(bb.w, 0.f);
#pragma unroll
                for (int q = 0; q < 4; q++) {
                    acc[q][0] = i0; acc[q][1] = i1; acc[q][2] = i2; acc[q][3] = i3;
                }
            }
            gemm4_k68p(sMark, roff, sW1p, h0, acc);
#pragma unroll
            for (int q = 0; q < 4; q++)
                *(float4*)(lhw + q * 132 + h0) =
                    make_float4(leaky(pairsum(acc[q][0])), leaky(pairsum(acc[q][1])),
                                leaky(pairsum(acc[q][2])), leaky(pairsum(acc[q][3])));
            __syncwarp();

            ull acc2[4][2];
            {
                float2 pb = *(const float2*)(sPcb2 + n2);
                ull b0 = pack2(pb.x, 0.f), b1 = pack2(pb.y, 0.f);
#pragma unroll
                for (int q = 0; q < 4; q++) { acc2[q][0] = b0; acc2[q][1] = b1; }
            }
#pragma unroll 1
            for (int k4 = 0; k4 < 32; k4++) {
                ulonglong2 x[4];
#pragma unroll
                for (int q = 0; q < 4; q++)
                    x[q] = *(const ulonglong2*)(lhw + q * 132 + 4 * k4);
#pragma unroll
                for (int half = 0; half < 2; half++) {
                    const int kp = 2 * k4 + half;
                    ulonglong2 w2 = *(const ulonglong2*)(sW2p + kp * 128 + n2 * 2);
#pragma unroll
                    for (int q = 0; q < 4; q++) {
                        ull xp = half ? x[q].y : x[q].x;
                        fma2(acc2[q][0], xp, w2.x);
                        fma2(acc2[q][1], xp, w2.y);
                    }
                }
            }
#pragma unroll
            for (int q = 0; q < 4; q++) {
                if (r0 + q < nn)
                    *(float2*)(sWB + rows[q] * 64 + n2) =
                        make_float2(pairsum(acc2[q][0]), pairsum(acc2[q][1]));
            }
            __syncwarp();
        }
        __syncthreads();

        {
            const int n = tid & 63, c = tid >> 6;
            float m = -1e30f;
            for (int j = c; j < nn; j += 8)
                m = fmaxf(m, sWB[rlist[j] * 64 + n]);
            sPMAX[c * 64 + n] = m;
        }
        __syncthreads();
        {
            const int n = tid & 63, c = tid >> 6;
            float mm = sPMAX[n];
#pragma unroll
            for (int c2 = 1; c2 < 8; c2++) mm = fmaxf(mm, sPMAX[c2 * 64 + n]);
            float s = 0.f;
            for (int j = c; j < nn; j += 8) {
                float e = __expf(sWB[rlist[j] * 64 + n] - mm);
                sWB[rlist[j] * 64 + n] = e;
                s += e;
            }
            sPSUM[c * 64 + n] = s;
        }
        __syncthreads();

        if (nn > 0) {
            float s0 = 0.f, s1 = 0.f;
#pragma unroll
            for (int c = 0; c < 8; c++) { s0 += sPSUM[c * 64 + lane]; s1 += sPSUM[c * 64 + lane + 32]; }
            const float sc0 = sC[ai * 64 + lane] / s0;
            const float sc1 = sC[ai * 64 + lane + 32] / s1;
            for (int j = w; j < nn; j += SW) {
                const int r = rlist[j];
                float v0 = fmaxf(sMark[r * 68 + lane]      - sWB[r * 64 + lane]      * sc0, 0.f);
                float v1 = fmaxf(sMark[r * 68 + lane + 32] - sWB[r * 64 + lane + 32] * sc1, 0.f);
                sMark[r * 68 + lane]      = v0;
                sMark[r * 68 + lane + 32] = v1;
                unsigned nzb = __ballot_sync(0xffffffffu, (v0 != 0.f) || (v1 != 0.f));
                if (lane == 0) rownz[r] = (nzb != 0) || (tailz[r] == 0);
            }
        }
        if (tid == 0) *snnz = 0;
        __syncthreads();
    }

    for (int i = tid; i < 129 * 68; i += ST) g_mark[b * 8772 + i] = sMark[i];
    for (int i = tid; i < 129; i += ST)      g_rnz[b * 129 + i]  = rownz[i];
}

// ---------- scoring kernel (round-6 verbatim: 4-row staged, 505 us) ----------
#define O2_JC   0
#define O2_JT   8704
#define O2_MK   17408
#define O2_JCB  26180
#define O2_JTB  26308
#define O2_JW2  26436
#define O2_JF   26564
#define O2_POOL 26692
#define O2_SWM  26820
#define O2_RL   26828
#define O2_NNZ  26960
#define SMEM2_FLOATS 26964
#define SMEM2_BYTES (SMEM2_FLOATS * 4)

__global__ __launch_bounds__(K2T, 1)
void score_kernel(const float* __restrict__ jcW1, const float* __restrict__ jcb1,
                  const float* __restrict__ jfW,  const float* __restrict__ jfb,
                  const float* __restrict__ jtW1, const float* __restrict__ jtb1,
                  const float* __restrict__ jtW2, const float* __restrict__ jtb2,
                  float* __restrict__ out)
{
    extern __shared__ float sm[];
    const int tid  = threadIdx.x;
    const int lane = tid & 31;
    const int w    = tid >> 5;
    const int t    = blockIdx.x;
    const int b    = blockIdx.y;
    const int h0   = lane * 4;

    float* sJc   = sm + O2_JC;
    float* sJt   = sm + O2_JT;
    float* sMk   = sm + O2_MK;
    float* sjcb  = sm + O2_JCB;
    float* sjtb  = sm + O2_JTB;
    float* sjw2  = sm + O2_JW2;
    float* sjf   = sm + O2_JF;
    float* spool = sm + O2_POOL;
    float* swm   = sm + O2_SWM;
    int*   rlist = (int*)(sm + O2_RL);
    int*   snnz  = (int*)(sm + O2_NNZ);

    for (int idx = tid; idx < 68 * 128; idx += K2T) {
        int k = idx >> 7, h = idx & 127;
        int d = pack_idx_128(k, h);
        sJc[d] = jcW1[t * 8704 + idx];
        sJt[d] = jtW1[t * 8704 + idx];
    }
    for (int idx = tid; idx < 2193; idx += K2T)
        ((float4*)sMk)[idx] = ((const float4*)(g_mark + b * 8772))[idx];
    if (tid < 128) {
        sjcb[tid]  = jcb1[t * 128 + tid];
        sjtb[tid]  = jtb1[t * 128 + tid];
        sjw2[tid]  = jtW2[t * 128 + tid];
        sjf[tid]   = jfW[tid];
        spool[tid] = 0.f;
    }
    if (tid == 192) *snnz = 0;
    __syncthreads();

    if (tid < 129) {
        if (g_rnz[b * 129 + tid]) {
            int p = atomicAdd(snnz, 1);
            rlist[p] = tid;
        }
    }
    __syncthreads();
    const int nn = *snnz;
    const int zr = (nn < 129);
    const int ntiles = (nn + 3) >> 2;
    const float jtb2v = jtb2[t];

    float pp0 = 0.f, pp1 = 0.f, pp2 = 0.f, pp3 = 0.f;
    for (int tile = w; tile < ntiles; tile += K2W) {
        const int r0 = tile * 4;
        int roff[4];
#pragma unroll
        for (int q = 0; q < 4; q++) roff[q] = rlist[min(r0 + q, nn - 1)] * 68;
        ull acc[4][4];
        {
            float4 pb = *(const float4*)(sjcb + h0);
            ull i0 = pack2(pb.x, 0.f), i1 = pack2(pb.y, 0.f),
                i2 = pack2(pb.z, 0.f), i3 = pack2(pb.w, 0.f);
#pragma unroll
            for (int q = 0; q < 4; q++) {
                acc[q][0] = i0; acc[q][1] = i1; acc[q][2] = i2; acc[q][3] = i3;
            }
        }
        gemm4_k68p(sMk, roff, sJc, h0, acc);
#pragma unroll
        for (int q = 0; q < 4; q++) {
            if (r0 + q < nn) {
                pp0 += leaky(pairsum(acc[q][0]));
                pp1 += leaky(pairsum(acc[q][1]));
                pp2 += leaky(pairsum(acc[q][2]));
                pp3 += leaky(pairsum(acc[q][3]));
            }
        }
    }
    atomicAdd(&spool[h0 + 0], pp0);
    atomicAdd(&spool[h0 + 1], pp1);
    atomicAdd(&spool[h0 + 2], pp2);
    atomicAdd(&spool[h0 + 3], pp3);

    const float w2a = sjw2[h0], w2b = sjw2[h0 + 1],
                w2c = sjw2[h0 + 2], w2d = sjw2[h0 + 3];
    float tmax = -1e30f;
    for (int tile = w; tile < ntiles; tile += K2W) {
        const int r0 = tile * 4;
        int roff[4];
#pragma unroll
        for (int q = 0; q < 4; q++) roff[q] = rlist[min(r0 + q, nn - 1)] * 68;
        ull acc[4][4];
        {
            float4 pb = *(const float4*)(sjtb + h0);
            ull i0 = pack2(pb.x, 0.f), i1 = pack2(pb.y, 0.f),
                i2 = pack2(pb.z, 0.f), i3 = pack2(pb.w, 0.f);
#pragma unroll
            for (int q = 0; q < 4; q++) {
                acc[q][0] = i0; acc[q][1] = i1; acc[q][2] = i2; acc[q][3] = i3;
            }
        }
        gemm4_k68p(sMk, roff, sJt, h0, acc);
#pragma unroll
        for (int q = 0; q < 4; q++) {
            float d = leaky(pairsum(acc[q][0])) * w2a
                    + leaky(pairsum(acc[q][1])) * w2b
                    + leaky(pairsum(acc[q][2])) * w2c
                    + leaky(pairsum(acc[q][3])) * w2d;
            d += __shfl_xor_sync(0xffffffffu, d, 16);
            d += __shfl_xor_sync(0xffffffffu, d, 8);
            d += __shfl_xor_sync(0xffffffffu, d, 4);
            d += __shfl_xor_sync(0xffffffffu, d, 2);
            d += __shfl_xor_sync(0xffffffffu, d, 1);
            if (r0 + q < nn) tmax = fmaxf(tmax, d + jtb2v);
        }
    }
    if (lane == 0) swm[w] = tmax;
    __syncthreads();

    if (w == 0) {
        float zs = leaky(sjtb[h0])     * w2a + leaky(sjtb[h0 + 1]) * w2b
                 + leaky(sjtb[h0 + 2]) * w2c + leaky(sjtb[h0 + 3]) * w2d;
        zs += __shfl_xor_sync(0xffffffffu, zs, 16);
        zs += __shfl_xor_sync(0xffffffffu, zs, 8);
        zs += __shfl_xor_sync(0xffffffffu, zs, 4);
        zs += __shfl_xor_sync(0xffffffffu, zs, 2);
        zs += __shfl_xor_sync(0xffffffffu, zs, 1);

        float pr = spool[lane]      * sjf[lane]
                 + spool[lane + 32] * sjf[lane + 32]
                 + spool[lane + 64] * sjf[lane + 64]
                 + spool[lane + 96] * sjf[lane + 96];
        pr += __shfl_xor_sync(0xffffffffu, pr, 16);
        pr += __shfl_xor_sync(0xffffffffu, pr, 8);
        pr += __shfl_xor_sync(0xffffffffu, pr, 4);
        pr += __shfl_xor_sync(0xffffffffu, pr, 2);
        pr += __shfl_xor_sync(0xffffffffu, pr, 1);
        if (lane == 0) {
            float res = 1.f / (1.f + expf(-(pr + jfb[0])));
            res = fmaxf(res, 1e-5f);
            float tm = swm[0];
#pragma unroll
            for (int j = 1; j < K2W; j++) tm = fmaxf(tm, swm[j]);
            if (zr) tm = fmaxf(tm, zs + jtb2v);
            out[b * TNN + t] = res * tm - 0.01f * expf(res);
        }
    }
}

// no-op kernel: shifts capture position so the profiled launch = petri_scan
__global__ void dummy_k() {}

extern "C" void kernel_launch(void* const* d_in, const int* in_sizes, int n_in,
                              void* d_out, int out_size) {
    (void)in_sizes; (void)n_in; (void)out_size;
    cudaFuncSetAttribute(petri_scan,
                         cudaFuncAttributeMaxDynamicSharedMemorySize, SMEM_BYTES);
    cudaFuncSetAttribute(score_kernel,
                         cudaFuncAttributeMaxDynamicSharedMemorySize, SMEM2_BYTES);
    // Capture = our 4th launch (established R14): make it the scan.
    dummy_k<<<1, 32>>>();
    dummy_k<<<1, 32>>>();
    dummy_k<<<1, 32>>>();
    petri_scan<<<BB, ST, SMEM_BYTES>>>(
        (const float*)d_in[0], (const float*)d_in[1], (const float*)d_in[2],
        (const float*)d_in[3], (const float*)d_in[4], (const float*)d_in[5],
        (const float*)d_in[6], (const float*)d_in[7]);
    score_kernel<<<dim3(TNN, BB), K2T, SMEM2_BYTES>>>(
        (const float*)d_in[8],  (const float*)d_in[9],  (const float*)d_in[10],
        (const float*)d_in[11], (const float*)d_in[12], (const float*)d_in[13],
        (const float*)d_in[14], (const float*)d_in[15], (float*)d_out);
}

// round 16
// speedup vs baseline: 1.0745x; 1.0099x over previous
#include <cuda_runtime.h>

#define BB 128
#define LL 128
#define TNN 32
#define ST 512
#define SW 16
#define K2T 256
#define K2W 8

typedef unsigned long long ull;

// inter-kernel scratch (device globals: allowed; no allocation)
__device__ float g_mark[BB * 129 * 68];
__device__ int   g_rnz[BB * 129];

// ---------- packed f32x2 helpers ----------
__device__ __forceinline__ ull pack2(float x, float y) {
    ull r; asm("mov.b64 %0, {%1,%2};" : "=l"(r) : "f"(x), "f"(y)); return r;
}
__device__ __forceinline__ void unpack2(ull v, float& x, float& y) {
    asm("mov.b64 {%0,%1}, %2;" : "=f"(x), "=f"(y) : "l"(v));
}
__device__ __forceinline__ void fma2(ull& d, ull a, ull b) {
    asm("fma.rn.f32x2 %0, %1, %2, %0;" : "+l"(d) : "l"(a), "l"(b));
}
__device__ __forceinline__ float pairsum(ull v) {
    float x, y; unpack2(v, x, y); return x + y;
}
__device__ __forceinline__ float leaky(float v) { return v > 0.f ? v : 0.01f * v; }

// Conflict-free k-pair packed index for a [K x 128] weight:
__device__ __forceinline__ int pack_idx_128(int k, int h) {
    return ((k >> 1) << 8) + (((h >> 1) & 1) << 7) + (h & ~3) + ((h & 1) << 1) + (k & 1);
}

// 4-row K=68 microkernel with x staging (proven optimum for this shape).
__device__ __forceinline__ void gemm4_k68p(const float* __restrict__ smk,
                                           const int* roff,
                                           const float* __restrict__ wp,
                                           int h0, ull acc[4][4]) {
#pragma unroll 1
    for (int k4 = 0; k4 < 17; k4++) {
        ulonglong2 x[4];
#pragma unroll
        for (int q = 0; q < 4; q++)
            x[q] = *(const ulonglong2*)(smk + roff[q] + 4 * k4);
#pragma unroll
        for (int half = 0; half < 2; half++) {
            const int kp = 2 * k4 + half;
            ulonglong2 wa = *(const ulonglong2*)(wp + kp * 256 + h0);
            ulonglong2 wb = *(const ulonglong2*)(wp + kp * 256 + 128 + h0);
#pragma unroll
            for (int q = 0; q < 4; q++) {
                ull xp = half ? x[q].y : x[q].x;
                fma2(acc[q][0], xp, wa.x);
                fma2(acc[q][1], xp, wa.y);
                fma2(acc[q][2], xp, wb.x);
                fma2(acc[q][3], xp, wb.y);
            }
        }
    }
}

// ---------- scan kernel shared memory layout (floats) ----------
#define OFF_W1P  0
#define OFF_W1C  8704
#define OFF_W2P  17408
#define OFF_MARK 25600
#define OFF_WB   34372
#define OFF_LH   42628
#define OFF_PMAX 51076    /* 1024 region: warp-max (16x64) then psum chunks (8x64) */
#define OFF_SMX2 52100    /* 64 : folded column max */
#define OFF_PCB1 52164
#define OFF_PCB2 52292
#define OFF_BD   52356
#define OFF_G    52996
#define OFF_C    55108
#define OFF_TE   57156
#define OFF_RNZ  57284
#define OFF_TLZ  57413
#define OFF_GNZ  57542
#define OFF_RLIST 57576
#define OFF_NNZ  57704
#define SMEM_FLOATS 57708
#define SMEM_BYTES (SMEM_FLOATS * 4)

__global__ __launch_bounds__(ST, 1)
void petri_scan(const float* __restrict__ bd,   const float* __restrict__ G,
                const float* __restrict__ C,    const float* __restrict__ Temb,
                const float* __restrict__ pcW1, const float* __restrict__ pcb1,
                const float* __restrict__ pcW2, const float* __restrict__ pcb2)
{
    extern __shared__ float sm[];
    const int tid  = threadIdx.x;
    const int lane = tid & 31;
    const int w    = tid >> 5;
    const int b    = blockIdx.x;
    const int h0   = lane * 4;
    const int n2   = lane * 2;

    float* sW1p  = sm + OFF_W1P;
    float* sW1c  = sm + OFF_W1C;
    float* sW2p  = sm + OFF_W2P;
    float* sMark = sm + OFF_MARK;
    float* sWB   = sm + OFF_WB;
    float* sLH   = sm + OFF_LH;
    float* sWMAX = sm + OFF_PMAX;      // 16 x 64 warp maxima
    float* sPCH  = sm + OFF_PMAX;      // 8 x 64 psum chunks (reused after fold)
    float* sSMX  = sm + OFF_SMX2;
    float* sPcb1 = sm + OFF_PCB1;
    float* sPcb2 = sm + OFF_PCB2;
    float* sBD   = sm + OFF_BD;
    float* sG    = sm + OFF_G;
    float* sC    = sm + OFF_C;
    float* sTe   = sm + OFF_TE;
    int*   rownz = (int*)(sm + OFF_RNZ);
    int*   tailz = (int*)(sm + OFF_TLZ);
    int*   gnzf  = (int*)(sm + OFF_GNZ);
    int*   rlist = (int*)(sm + OFF_RLIST);
    int*   snnz  = (int*)(sm + OFF_NNZ);

    for (int idx = tid; idx < 68 * 128; idx += ST) {
        int k = idx >> 7, h = idx & 127;
        sW1p[pack_idx_128(k, h)] = pcW1[idx];
        sW1c[idx] = pcW1[68 * 128 + idx];
    }
    for (int idx = tid; idx < 128 * 64; idx += ST) {
        int k = idx >> 6, n = idx & 63;
        sW2p[((k >> 1) << 7) + (n << 1) + (k & 1)] = pcW2[idx];
    }
    if (tid < 128) sPcb1[tid] = pcb1[tid];
    else if (tid < 192) sPcb2[tid - 128] = pcb2[tid - 128];
    for (int i = tid; i < 640; i += ST) sBD[i] = bd[b * 640 + i];
    for (int i = tid; i < 33 * 64; i += ST) sG[i] = fmaxf(G[i], 0.f);
    for (int i = tid; i < 32 * 64; i += ST) sC[i] = fmaxf(C[i], 0.f);
    if (tid < 128) sTe[tid] = Temb[tid];
    for (int i = tid; i < 129 * 68; i += ST) sMark[i] = 0.f;
    if (tid < 129) { rownz[tid] = 0; tailz[tid] = 1; }
    if (tid == 200) *snnz = 0;
    __syncthreads();
    if (tid < 33) {
        int nz = 0;
        for (int c = 0; c < 64; c++) nz |= (sG[tid * 64 + c] != 0.f);
        gnzf[tid] = nz;
    } else if (tid >= 64 && tid < 128) {
        sMark[tid - 64] = sG[tid - 64];
    }
    __syncthreads();

    // ---- prefill: ALL gen rows + flags are input-only; hoist out of the loop ----
    // Row i+1 content is never read at step i, so prefilling is exact.
    for (int idx = tid; idx < 128 * 68; idx += ST) {
        const int i = idx / 68, c = idx - i * 68;
        const int a = (int)sBD[i];
        if (a > 0 && a != TNN + 1) {
            float v = (c < 64) ? sG[a * 64 + c] : sBD[(c - 63) * 128 + i];
            sMark[(i + 1) * 68 + c] = v;
        }
    }
    if (tid < 128) {
        const int a = (int)sBD[tid];
        if (a > 0 && a != TNN + 1) {
            float t0 = sBD[128 + tid], t1 = sBD[256 + tid],
                  t2 = sBD[384 + tid], t3 = sBD[512 + tid];
            int tz = (t0 == 0.f) && (t1 == 0.f) && (t2 == 0.f) && (t3 == 0.f);
            tailz[tid + 1] = tz;
            rownz[tid + 1] = (gnzf[a] != 0) || !tz;
        }
    }
    if (tid == 0) rownz[0] = gnzf[0];

    // precompute 32 base vectors (pcb1 folded in)
    for (int idx = tid; idx < 32 * 128; idx += ST) {
        const int aa = idx >> 7, h = idx & 127;
        const float* cv = sC + aa * 64;
        const float* wc = sW1c + h;
        float s = sPcb1[h];
#pragma unroll 4
        for (int j = 0; j < 64; j++)
            s = fmaf(cv[j], wc[j << 7], s);
        const float* tv = sTe + aa * 4;
#pragma unroll
        for (int j = 0; j < 4; j++)
            s = fmaf(tv[j], wc[(64 + j) << 7], s);
        sWB[idx] = s;
    }
    __syncthreads();
    for (int idx = tid; idx < 32 * 128; idx += ST) sW1c[idx] = sWB[idx];
    __syncthreads();
    const float* sBaseAll = sW1c;

    float* lhw = sLH + w * 528;

    for (int i = 0; i < LL; i++) {
        const int a = (int)sBD[i];
        if (a <= 0 || a == TNN + 1) continue;
        const int ai = a - 1;
        const int nrows = i + 1;

        // ---- Phase A: compaction only (gen rows prefilled) ----
        if (tid < 128) {
            if (tid < nrows && rownz[tid]) {
                int p = atomicAdd(snnz, 1);
                rlist[p] = tid;
            }
        }
        __syncthreads();

        const int nn = *snnz;
        const int ntiles = (nn + 3) >> 2;

        // ---- Phase B + warp-local column max ----
        float wm0 = -1e30f, wm1 = -1e30f;
        for (int tile = w; tile < ntiles; tile += SW) {
            const int r0 = tile * 4;
            int rows[4], roff[4];
#pragma unroll
            for (int q = 0; q < 4; q++) {
                rows[q] = rlist[min(r0 + q, nn - 1)];
                roff[q] = rows[q] * 68;
            }

            ull acc[4][4];
            {
                float4 bb = *(const float4*)(sBaseAll + ai * 128 + h0);
                ull i0 = pack2(bb.x, 0.f), i1 = pack2(bb.y, 0.f),
                    i2 = pack2(bb.z, 0.f), i3 = pack2(bb.w, 0.f);
#pragma unroll
                for (int q = 0; q < 4; q++) {
                    acc[q][0] = i0; acc[q][1] = i1; acc[q][2] = i2; acc[q][3] = i3;
                }
            }
            gemm4_k68p(sMark, roff, sW1p, h0, acc);
#pragma unroll
            for (int q = 0; q < 4; q++)
                *(float4*)(lhw + q * 132 + h0) =
                    make_float4(leaky(pairsum(acc[q][0])), leaky(pairsum(acc[q][1])),
                                leaky(pairsum(acc[q][2])), leaky(pairsum(acc[q][3])));
            __syncwarp();

            ull acc2[4][2];
            {
                float2 pb = *(const float2*)(sPcb2 + n2);
                ull b0 = pack2(pb.x, 0.f), b1 = pack2(pb.y, 0.f);
#pragma unroll
                for (int q = 0; q < 4; q++) { acc2[q][0] = b0; acc2[q][1] = b1; }
            }
#pragma unroll 1
            for (int k4 = 0; k4 < 32; k4++) {
                ulonglong2 x[4];
#pragma unroll
                for (int q = 0; q < 4; q++)
                    x[q] = *(const ulonglong2*)(lhw + q * 132 + 4 * k4);
#pragma unroll
                for (int half = 0; half < 2; half++) {
                    const int kp = 2 * k4 + half;
                    ulonglong2 w2 = *(const ulonglong2*)(sW2p + kp * 128 + n2 * 2);
#pragma unroll
                    for (int q = 0; q < 4; q++) {
                        ull xp = half ? x[q].y : x[q].x;
                        fma2(acc2[q][0], xp, w2.x);
                        fma2(acc2[q][1], xp, w2.y);
                    }
                }
            }
#pragma unroll
            for (int q = 0; q < 4; q++) {
                if (r0 + q < nn) {
                    float v0 = pairsum(acc2[q][0]), v1 = pairsum(acc2[q][1]);
                    *(float2*)(sWB + rows[q] * 64 + n2) = make_float2(v0, v1);
                    wm0 = fmaxf(wm0, v0);
                    wm1 = fmaxf(wm1, v1);
                }
            }
            __syncwarp();
        }
        sWMAX[w * 64 + n2]     = wm0;
        sWMAX[w * 64 + n2 + 1] = wm1;
        __syncthreads();

        // ---- fold 16 warp maxima -> sSMX (64 threads) ----
        if (tid < 64) {
            float m = sWMAX[tid];
#pragma unroll
            for (int j = 1; j < 16; j++) m = fmaxf(m, sWMAX[j * 64 + tid]);
            sSMX[tid] = m;
        }
        __syncthreads();

        // ---- exp pass: e = exp(w - mm), chunked partial sums ----
        {
            const int n = tid & 63, c = tid >> 6;
            const float mm = sSMX[n];
            float s = 0.f;
            for (int j = c; j < nn; j += 8) {
                float e = __expf(sWB[rlist[j] * 64 + n] - mm);
                sWB[rlist[j] * 64 + n] = e;
                s += e;
            }
            sPCH[c * 64 + n] = s;
        }
        __syncthreads();

        // ---- Phase D: marking update + zmask maintenance ----
        if (nn > 0) {
            float s0 = 0.f, s1 = 0.f;
#pragma unroll
            for (int c = 0; c < 8; c++) { s0 += sPCH[c * 64 + lane]; s1 += sPCH[c * 64 + lane + 32]; }
            const float sc0 = sC[ai * 64 + lane] / s0;
            const float sc1 = sC[ai * 64 + lane + 32] / s1;
            for (int j = w; j < nn; j += SW) {
                const int r = rlist[j];
                float v0 = fmaxf(sMark[r * 68 + lane]      - sWB[r * 64 + lane]      * sc0, 0.f);
                float v1 = fmaxf(sMark[r * 68 + lane + 32] - sWB[r * 64 + lane + 32] * sc1, 0.f);
                sMark[r * 68 + lane]      = v0;
                sMark[r * 68 + lane + 32] = v1;
                unsigned nzb = __ballot_sync(0xffffffffu, (v0 != 0.f) || (v1 != 0.f));
                if (lane == 0) rownz[r] = (nzb != 0) || (tailz[r] == 0);
            }
        }
        if (tid == 0) *snnz = 0;
        __syncthreads();
    }

    for (int i = tid; i < 129 * 68; i += ST) g_mark[b * 8772 + i] = sMark[i];
    for (int i = tid; i < 129; i += ST)      g_rnz[b * 129 + i]  = rownz[i];
}

// ---------- scoring kernel (round-6 verbatim: 4-row staged, 505 us) ----------
#define O2_JC   0
#define O2_JT   8704
#define O2_MK   17408
#define O2_JCB  26180
#define O2_JTB  26308
#define O2_JW2  26436
#define O2_JF   26564
#define O2_POOL 26692
#define O2_SWM  26820
#define O2_RL   26828
#define O2_NNZ  26960
#define SMEM2_FLOATS 26964
#define SMEM2_BYTES (SMEM2_FLOATS * 4)

__global__ __launch_bounds__(K2T, 1)
void score_kernel(const float* __restrict__ jcW1, const float* __restrict__ jcb1,
                  const float* __restrict__ jfW,  const float* __restrict__ jfb,
                  const float* __restrict__ jtW1, const float* __restrict__ jtb1,
                  const float* __restrict__ jtW2, const float* __restrict__ jtb2,
                  float* __restrict__ out)
{
    extern __shared__ float sm[];
    const int tid  = threadIdx.x;
    const int lane = tid & 31;
    const int w    = tid >> 5;
    const int t    = blockIdx.x;
    const int b    = blockIdx.y;
    const int h0   = lane * 4;

    float* sJc   = sm + O2_JC;
    float* sJt   = sm + O2_JT;
    float* sMk   = sm + O2_MK;
    float* sjcb  = sm + O2_JCB;
    float* sjtb  = sm + O2_JTB;
    float* sjw2  = sm + O2_JW2;
    float* sjf   = sm + O2_JF;
    float* spool = sm + O2_POOL;
    float* swm   = sm + O2_SWM;
    int*   rlist = (int*)(sm + O2_RL);
    int*   snnz  = (int*)(sm + O2_NNZ);

    for (int idx = tid; idx < 68 * 128; idx += K2T) {
        int k = idx >> 7, h = idx & 127;
        int d = pack_idx_128(k, h);
        sJc[d] = jcW1[t * 8704 + idx];
        sJt[d] = jtW1[t * 8704 + idx];
    }
    for (int idx = tid; idx < 2193; idx += K2T)
        ((float4*)sMk)[idx] = ((const float4*)(g_mark + b * 8772))[idx];
    if (tid < 128) {
        sjcb[tid]  = jcb1[t * 128 + tid];
        sjtb[tid]  = jtb1[t * 128 + tid];
        sjw2[tid]  = jtW2[t * 128 + tid];
        sjf[tid]   = jfW[tid];
        spool[tid] = 0.f;
    }
    if (tid == 192) *snnz = 0;
    __syncthreads();

    if (tid < 129) {
        if (g_rnz[b * 129 + tid]) {
            int p = atomicAdd(snnz, 1);
            rlist[p] = tid;
        }
    }
    __syncthreads();
    const int nn = *snnz;
    const int zr = (nn < 129);
    const int ntiles = (nn + 3) >> 2;
    const float jtb2v = jtb2[t];

    float pp0 = 0.f, pp1 = 0.f, pp2 = 0.f, pp3 = 0.f;
    for (int tile = w; tile < ntiles; tile += K2W) {
        const int r0 = tile * 4;
        int roff[4];
#pragma unroll
        for (int q = 0; q < 4; q++) roff[q] = rlist[min(r0 + q, nn - 1)] * 68;
        ull acc[4][4];
        {
            float4 pb = *(const float4*)(sjcb + h0);
            ull i0 = pack2(pb.x, 0.f), i1 = pack2(pb.y, 0.f),
                i2 = pack2(pb.z, 0.f), i3 = pack2(pb.w, 0.f);
#pragma unroll
            for (int q = 0; q < 4; q++) {
                acc[q][0] = i0; acc[q][1] = i1; acc[q][2] = i2; acc[q][3] = i3;
            }
        }
        gemm4_k68p(sMk, roff, sJc, h0, acc);
#pragma unroll
        for (int q = 0; q < 4; q++) {
            if (r0 + q < nn) {
                pp0 += leaky(pairsum(acc[q][0]));
                pp1 += leaky(pairsum(acc[q][1]));
                pp2 += leaky(pairsum(acc[q][2]));
                pp3 += leaky(pairsum(acc[q][3]));
            }
        }
    }
    atomicAdd(&spool[h0 + 0], pp0);
    atomicAdd(&spool[h0 + 1], pp1);
    atomicAdd(&spool[h0 + 2], pp2);
    atomicAdd(&spool[h0 + 3], pp3);

    const float w2a = sjw2[h0], w2b = sjw2[h0 + 1],
                w2c = sjw2[h0 + 2], w2d = sjw2[h0 + 3];
    float tmax = -1e30f;
    for (int tile = w; tile < ntiles; tile += K2W) {
        const int r0 = tile * 4;
        int roff[4];
#pragma unroll
        for (int q = 0; q < 4; q++) roff[q] = rlist[min(r0 + q, nn - 1)] * 68;
        ull acc[4][4];
        {
            float4 pb = *(const float4*)(sjtb + h0);
            ull i0 = pack2(pb.x, 0.f), i1 = pack2(pb.y, 0.f),
                i2 = pack2(pb.z, 0.f), i3 = pack2(pb.w, 0.f);
#pragma unroll
            for (int q = 0; q < 4; q++) {
                acc[q][0] = i0; acc[q][1] = i1; acc[q][2] = i2; acc[q][3] = i3;
            }
        }
        gemm4_k68p(sMk, roff, sJt, h0, acc);
#pragma unroll
        for (int q = 0; q < 4; q++) {
            float d = leaky(pairsum(acc[q][0])) * w2a
                    + leaky(pairsum(acc[q][1])) * w2b
                    + leaky(pairsum(acc[q][2])) * w2c
                    + leaky(pairsum(acc[q][3])) * w2d;
            d += __shfl_xor_sync(0xffffffffu, d, 16);
            d += __shfl_xor_sync(0xffffffffu, d, 8);
            d += __shfl_xor_sync(0xffffffffu, d, 4);
            d += __shfl_xor_sync(0xffffffffu, d, 2);
            d += __shfl_xor_sync(0xffffffffu, d, 1);
            if (r0 + q < nn) tmax = fmaxf(tmax, d + jtb2v);
        }
    }
    if (lane == 0) swm[w] = tmax;
    __syncthreads();

    if (w == 0) {
        float zs = leaky(sjtb[h0])     * w2a + leaky(sjtb[h0 + 1]) * w2b
                 + leaky(sjtb[h0 + 2]) * w2c + leaky(sjtb[h0 + 3]) * w2d;
        zs += __shfl_xor_sync(0xffffffffu, zs, 16);
        zs += __shfl_xor_sync(0xffffffffu, zs, 8);
        zs += __shfl_xor_sync(0xffffffffu, zs, 4);
        zs += __shfl_xor_sync(0xffffffffu, zs, 2);
        zs += __shfl_xor_sync(0xffffffffu, zs, 1);

        float pr = spool[lane]      * sjf[lane]
                 + spool[lane + 32] * sjf[lane + 32]
                 + spool[lane + 64] * sjf[lane + 64]
                 + spool[lane + 96] * sjf[lane + 96];
        pr += __shfl_xor_sync(0xffffffffu, pr, 16);
        pr += __shfl_xor_sync(0xffffffffu, pr, 8);
        pr += __shfl_xor_sync(0xffffffffu, pr, 4);
        pr += __shfl_xor_sync(0xffffffffu, pr, 2);
        pr += __shfl_xor_sync(0xffffffffu, pr, 1);
        if (lane == 0) {
            float res = 1.f / (1.f + expf(-(pr + jfb[0])));
            res = fmaxf(res, 1e-5f);
            float tm = swm[0];
#pragma unroll
            for (int j = 1; j < K2W; j++) tm = fmaxf(tm, swm[j]);
            if (zr) tm = fmaxf(tm, zs + jtb2v);
            out[b * TNN + t] = res * tm - 0.01f * expf(res);
        }
    }
}

// no-op kernel: shifts capture position so the profiled launch = petri_scan
__global__ void dummy_k() {}

extern "C" void kernel_launch(void* const* d_in, const int* in_sizes, int n_in,
                              void* d_out, int out_size) {
    (void)in_sizes; (void)n_in; (void)out_size;
    cudaFuncSetAttribute(petri_scan,
                         cudaFuncAttributeMaxDynamicSharedMemorySize, SMEM_BYTES);
    cudaFuncSetAttribute(score_kernel,
                         cudaFuncAttributeMaxDynamicSharedMemorySize, SMEM2_BYTES);
    dummy_k<<<1, 32>>>();
    dummy_k<<<1, 32>>>();
    dummy_k<<<1, 32>>>();
    petri_scan<<<BB, ST, SMEM_BYTES>>>(
        (const float*)d_in[0], (const float*)d_in[1], (const float*)d_in[2],
        (const float*)d_in[3], (const float*)d_in[4], (const float*)d_in[5],
        (const float*)d_in[6], (const float*)d_in[7]);
    score_kernel<<<dim3(TNN, BB), K2T, SMEM2_BYTES>>>(
        (const float*)d_in[8],  (const float*)d_in[9],  (const float*)d_in[10],
        (const float*)d_in[11], (const float*)d_in[12], (const float*)d_in[13],
        (const float*)d_in[14], (const float*)d_in[15], (float*)d_out);
}